// round 1
// baseline (speedup 1.0000x reference)
#include <cuda_runtime.h>
#include <math.h>

#define BB 8
#define NN 4096
#define MM 4096
#define DD 128

#define TILE 128
#define KC   32
#define PAD  36   // row stride in floats for smem tiles (128 k-cols + pad, 16B-aligned rows)

// Scratch (device globals: no allocation allowed in kernel_launch)
__device__ float g_rowmin[BB * NN];  // min over j (M) of d^2 for each (b,i)  -> precision
__device__ float g_colmin[BB * MM];  // min over i (N) of d^2 for each (b,j)  -> coverage
__device__ float g_x2[BB * NN];
__device__ float g_y2[BB * MM];

__global__ void init_mins_kernel() {
    int t = blockIdx.x * blockDim.x + threadIdx.x;
    if (t < BB * NN) {
        g_rowmin[t] = __int_as_float(0x7F800000);  // +inf
        g_colmin[t] = __int_as_float(0x7F800000);
    }
}

// One warp per row: squared L2 norms of x and y rows.
__global__ void norms_kernel(const float* __restrict__ x, const float* __restrict__ y) {
    int gw   = (blockIdx.x * blockDim.x + threadIdx.x) >> 5;
    int lane = threadIdx.x & 31;
    const float* src;
    float* dst;
    int row;
    if (gw < BB * NN) { src = x; dst = g_x2; row = gw; }
    else              { src = y; dst = g_y2; row = gw - BB * NN; }
    const float4* p = reinterpret_cast<const float4*>(src + (size_t)row * DD);
    float4 v = p[lane];                       // 32 lanes * 4 = 128 = DD
    float s = v.x * v.x + v.y * v.y + v.z * v.z + v.w * v.w;
    #pragma unroll
    for (int o = 16; o; o >>= 1) s += __shfl_xor_sync(0xFFFFFFFFu, s, o);
    if (lane == 0) dst[row] = s;
}

// Fused tiled distance^2 + row/col min kernel.
// Block: 16x16 threads, 128x128 output tile, 8x8 micro-tile per thread.
__global__ __launch_bounds__(256, 2)
void chamfer_tile_kernel(const float* __restrict__ x, const float* __restrict__ y) {
    __shared__ float xs[TILE * PAD];   // xs[row][k], row stride PAD
    __shared__ float ys[TILE * PAD];

    const int t  = threadIdx.x;
    const int tx = t & 15;
    const int ty = t >> 4;

    const int b  = blockIdx.z;
    const int i0 = blockIdx.x * TILE;  // x rows
    const int j0 = blockIdx.y * TILE;  // y rows

    const float* xp = x + ((size_t)b * NN + i0) * DD;
    const float* yp = y + ((size_t)b * MM + j0) * DD;

    float acc[8][8];
    #pragma unroll
    for (int r = 0; r < 8; r++)
        #pragma unroll
        for (int c = 0; c < 8; c++) acc[r][c] = 0.0f;

    for (int kc = 0; kc < DD; kc += KC) {
        // Load 128x32 chunk of each matrix: 1024 float4 per matrix, 4 per thread.
        #pragma unroll
        for (int p = 0; p < 4; p++) {
            int q   = t + p * 256;
            int row = q >> 3;          // 0..127
            int c4  = q & 7;           // 0..7 float4 within 32-float chunk
            float4 vx = *reinterpret_cast<const float4*>(xp + (size_t)row * DD + kc + c4 * 4);
            float4 vy = *reinterpret_cast<const float4*>(yp + (size_t)row * DD + kc + c4 * 4);
            *reinterpret_cast<float4*>(&xs[row * PAD + c4 * 4]) = vx;
            *reinterpret_cast<float4*>(&ys[row * PAD + c4 * 4]) = vy;
        }
        __syncthreads();

        #pragma unroll
        for (int k = 0; k < KC; k++) {
            float xr[8], yr[8];
            #pragma unroll
            for (int r = 0; r < 8; r++) xr[r] = xs[(ty + r * 16) * PAD + k];
            #pragma unroll
            for (int c = 0; c < 8; c++) yr[c] = ys[(tx + c * 16) * PAD + k];
            #pragma unroll
            for (int r = 0; r < 8; r++)
                #pragma unroll
                for (int c = 0; c < 8; c++)
                    acc[r][c] = fmaf(xr[r], yr[c], acc[r][c]);
        }
        __syncthreads();
    }

    // Epilogue: d^2 = ||x||^2 + ||y||^2 - 2<x,y>, clamp at 0; per-thread mins.
    float x2v[8], y2v[8];
    #pragma unroll
    for (int r = 0; r < 8; r++) x2v[r] = g_x2[(size_t)b * NN + i0 + ty + r * 16];
    #pragma unroll
    for (int c = 0; c < 8; c++) y2v[c] = g_y2[(size_t)b * MM + j0 + tx + c * 16];

    float rmin[8], cmin[8];
    #pragma unroll
    for (int r = 0; r < 8; r++) rmin[r] = __int_as_float(0x7F800000);
    #pragma unroll
    for (int c = 0; c < 8; c++) cmin[c] = __int_as_float(0x7F800000);

    #pragma unroll
    for (int r = 0; r < 8; r++) {
        #pragma unroll
        for (int c = 0; c < 8; c++) {
            float d2 = fmaxf(x2v[r] + y2v[c] - 2.0f * acc[r][c], 0.0f);
            rmin[r] = fminf(rmin[r], d2);
            cmin[c] = fminf(cmin[c], d2);
        }
    }

    // Cross-thread reduction of mins via smem (reuse xs; safe after last sync).
    float* red = xs;   // need 128*17 floats = 8704B < tile buffer

    // rows: row i = ty + r*16, partials across tx (16)
    #pragma unroll
    for (int r = 0; r < 8; r++) red[(ty + r * 16) * 17 + tx] = rmin[r];
    __syncthreads();
    if (t < 128) {
        float m = __int_as_float(0x7F800000);
        #pragma unroll
        for (int q = 0; q < 16; q++) m = fminf(m, red[t * 17 + q]);
        atomicMin((int*)&g_rowmin[(size_t)b * NN + i0 + t], __float_as_int(m));
    }
    __syncthreads();

    // cols: col j = tx + c*16, partials across ty (16)
    #pragma unroll
    for (int c = 0; c < 8; c++) red[(tx + c * 16) * 17 + ty] = cmin[c];
    __syncthreads();
    if (t < 128) {
        float m = __int_as_float(0x7F800000);
        #pragma unroll
        for (int q = 0; q < 16; q++) m = fminf(m, red[t * 17 + q]);
        atomicMin((int*)&g_colmin[(size_t)b * MM + j0 + t], __float_as_int(m));
    }
}

// Final: out = (sum_all sqrt(rowmin) + sum_all sqrt(colmin)) / (B*N)   (N == M)
__global__ void reduce_kernel(float* __restrict__ out) {
    __shared__ float sm[256];
    int tid = threadIdx.x;
    float s = 0.0f;
    for (int i = tid; i < BB * NN; i += 256)
        s += sqrtf(g_rowmin[i]) + sqrtf(g_colmin[i]);
    sm[tid] = s;
    __syncthreads();
    for (int o = 128; o > 0; o >>= 1) {
        if (tid < o) sm[tid] += sm[tid + o];
        __syncthreads();
    }
    if (tid == 0) out[0] = sm[0] / (float)(BB * NN);
}

extern "C" void kernel_launch(void* const* d_in, const int* in_sizes, int n_in,
                              void* d_out, int out_size) {
    const float* x = (const float*)d_in[0];
    const float* y = (const float*)d_in[1];
    float* out = (float*)d_out;
    (void)in_sizes; (void)n_in; (void)out_size;

    init_mins_kernel<<<(BB * NN + 255) / 256, 256>>>();

    int total_warps = 2 * BB * NN;               // one warp per row, x then y
    norms_kernel<<<(total_warps * 32 + 255) / 256, 256>>>(x, y);

    dim3 grid(NN / TILE, MM / TILE, BB);         // (32, 32, 8)
    chamfer_tile_kernel<<<grid, 256>>>(x, y);

    reduce_kernel<<<1, 256>>>(out);
}

// round 2
// speedup vs baseline: 1.6816x; 1.6816x over previous
#include <cuda_runtime.h>
#include <math.h>

#define BB 8
#define NN 4096
#define MM 4096
#define DD 128

#define TILE 128
#define KC   32

// Scratch (no allocation allowed in kernel_launch)
__device__ float g_rowmin[BB * NN];  // min over j of d^2 per (b,i)
__device__ float g_colmin[BB * MM];  // min over i of d^2 per (b,j)
__device__ float g_x2[BB * NN];
__device__ float g_y2[BB * MM];
__device__ float g_partial[128];

__global__ void init_mins_kernel() {
    int t = blockIdx.x * blockDim.x + threadIdx.x;
    if (t < BB * NN) {
        g_rowmin[t] = __int_as_float(0x7F800000);
        g_colmin[t] = __int_as_float(0x7F800000);
    }
}

__global__ void norms_kernel(const float* __restrict__ x, const float* __restrict__ y) {
    int gw   = (blockIdx.x * blockDim.x + threadIdx.x) >> 5;
    int lane = threadIdx.x & 31;
    const float* src;
    float* dst;
    int row;
    if (gw < BB * NN) { src = x; dst = g_x2; row = gw; }
    else              { src = y; dst = g_y2; row = gw - BB * NN; }
    const float4* p = reinterpret_cast<const float4*>(src + (size_t)row * DD);
    float4 v = p[lane];
    float s = v.x * v.x + v.y * v.y + v.z * v.z + v.w * v.w;
    #pragma unroll
    for (int o = 16; o; o >>= 1) s += __shfl_xor_sync(0xFFFFFFFFu, s, o);
    if (lane == 0) dst[row] = s;
}

// smem index with XOR swizzle: tiles stored [k][row], 128 rows per k.
// Swizzle spreads banks for both float4-sourced stores and fragment loads (<=2-way).
__device__ __forceinline__ int SW(int k, int c) {
    return k * 128 + (c ^ ((((unsigned)k >> 1) & 7) << 2));
}

__device__ __forceinline__ void mma_tf32(float* c, const unsigned* a, const unsigned* b) {
    asm volatile(
        "mma.sync.aligned.m16n8k8.row.col.f32.tf32.tf32.f32 "
        "{%0,%1,%2,%3}, {%4,%5,%6,%7}, {%8,%9}, {%0,%1,%2,%3};"
        : "+f"(c[0]), "+f"(c[1]), "+f"(c[2]), "+f"(c[3])
        : "r"(a[0]), "r"(a[1]), "r"(a[2]), "r"(a[3]), "r"(b[0]), "r"(b[1]));
}

// 128x128 tile per block, 8 warps (2x4), warp tile 64x32, m16n8k8 TF32 mma.
__global__ __launch_bounds__(256, 2)
void chamfer_mma_kernel(const float* __restrict__ x, const float* __restrict__ y) {
    __shared__ float sm[2 * KC * TILE];   // xs then ys, 32KB total
    float* xs = sm;
    float* ys = sm + KC * TILE;

    const int t    = threadIdx.x;
    const int lane = t & 31;
    const int wid  = t >> 5;
    const int wi   = wid >> 2;   // 0..1  (64-row slab)
    const int wj   = wid & 3;    // 0..3  (32-col slab)
    const int g    = lane >> 2;  // 0..7
    const int tig  = lane & 3;   // 0..3

    const int b    = blockIdx.z;
    const int iblk = blockIdx.x * TILE;
    const int jblk = blockIdx.y * TILE;

    const float* xp = x + ((size_t)b * NN + iblk) * DD;
    const float* yp = y + ((size_t)b * MM + jblk) * DD;

    float acc[4][4][4];
    #pragma unroll
    for (int mt = 0; mt < 4; mt++)
        #pragma unroll
        for (int nt = 0; nt < 4; nt++)
            #pragma unroll
            for (int r = 0; r < 4; r++) acc[mt][nt][r] = 0.0f;

    const int ibase = wi * 64 + g;   // a-frag row base
    const int jbase = wj * 32 + g;   // b-frag col base

    for (int kc = 0; kc < DD; kc += KC) {
        // Stage 128x32 chunks of x and y, transposed [k][row], fp32 bits (fed as tf32).
        #pragma unroll
        for (int p = 0; p < 4; p++) {
            int q   = t + p * 256;
            int row = q >> 3;
            int c4  = (q & 7) * 4;
            float4 vx = *reinterpret_cast<const float4*>(xp + (size_t)row * DD + kc + c4);
            float4 vy = *reinterpret_cast<const float4*>(yp + (size_t)row * DD + kc + c4);
            xs[SW(c4 + 0, row)] = vx.x;  ys[SW(c4 + 0, row)] = vy.x;
            xs[SW(c4 + 1, row)] = vx.y;  ys[SW(c4 + 1, row)] = vy.y;
            xs[SW(c4 + 2, row)] = vx.z;  ys[SW(c4 + 2, row)] = vy.z;
            xs[SW(c4 + 3, row)] = vx.w;  ys[SW(c4 + 3, row)] = vy.w;
        }
        __syncthreads();

        #pragma unroll
        for (int ks = 0; ks < 4; ks++) {
            const int k0 = ks * 8;
            unsigned af[4][4], bf[4][2];
            #pragma unroll
            for (int mt = 0; mt < 4; mt++) {
                af[mt][0] = __float_as_uint(xs[SW(k0 + tig,     ibase + mt * 16)]);
                af[mt][1] = __float_as_uint(xs[SW(k0 + tig,     ibase + mt * 16 + 8)]);
                af[mt][2] = __float_as_uint(xs[SW(k0 + tig + 4, ibase + mt * 16)]);
                af[mt][3] = __float_as_uint(xs[SW(k0 + tig + 4, ibase + mt * 16 + 8)]);
            }
            #pragma unroll
            for (int nt = 0; nt < 4; nt++) {
                bf[nt][0] = __float_as_uint(ys[SW(k0 + tig,     jbase + nt * 8)]);
                bf[nt][1] = __float_as_uint(ys[SW(k0 + tig + 4, jbase + nt * 8)]);
            }
            #pragma unroll
            for (int mt = 0; mt < 4; mt++)
                #pragma unroll
                for (int nt = 0; nt < 4; nt++)
                    mma_tf32(acc[mt][nt], af[mt], bf[nt]);
        }
        __syncthreads();
    }

    // Epilogue: d2 = x2 + y2 - 2*dot, clamp; per-thread row/col mins.
    // C frag: c0=(g,2tig) c1=(g,2tig+1) c2=(g+8,2tig) c3=(g+8,2tig+1)
    float x2v[4][2], y2v[4][2];
    #pragma unroll
    for (int mt = 0; mt < 4; mt++) {
        x2v[mt][0] = g_x2[(size_t)b * NN + iblk + wi * 64 + mt * 16 + g];
        x2v[mt][1] = g_x2[(size_t)b * NN + iblk + wi * 64 + mt * 16 + g + 8];
    }
    #pragma unroll
    for (int nt = 0; nt < 4; nt++) {
        y2v[nt][0] = g_y2[(size_t)b * MM + jblk + wj * 32 + nt * 8 + 2 * tig];
        y2v[nt][1] = g_y2[(size_t)b * MM + jblk + wj * 32 + nt * 8 + 2 * tig + 1];
    }

    const float INF = __int_as_float(0x7F800000);
    float rmin[4][2], cmin[4][2];
    #pragma unroll
    for (int a_ = 0; a_ < 4; a_++) { rmin[a_][0] = rmin[a_][1] = INF; cmin[a_][0] = cmin[a_][1] = INF; }

    #pragma unroll
    for (int mt = 0; mt < 4; mt++)
        #pragma unroll
        for (int nt = 0; nt < 4; nt++)
            #pragma unroll
            for (int rr = 0; rr < 2; rr++)
                #pragma unroll
                for (int cc = 0; cc < 2; cc++) {
                    float d2 = fmaxf(x2v[mt][rr] + y2v[nt][cc] - 2.0f * acc[mt][nt][rr * 2 + cc], 0.0f);
                    rmin[mt][rr] = fminf(rmin[mt][rr], d2);
                    cmin[nt][cc] = fminf(cmin[nt][cc], d2);
                }

    // rmin: reduce across tig (quad lanes L^1, L^2)
    #pragma unroll
    for (int mt = 0; mt < 4; mt++)
        #pragma unroll
        for (int rr = 0; rr < 2; rr++) {
            float v = rmin[mt][rr];
            v = fminf(v, __shfl_xor_sync(0xFFFFFFFFu, v, 1));
            v = fminf(v, __shfl_xor_sync(0xFFFFFFFFu, v, 2));
            rmin[mt][rr] = v;
        }
    // cmin: reduce across g (lanes L^4, L^8, L^16)
    #pragma unroll
    for (int nt = 0; nt < 4; nt++)
        #pragma unroll
        for (int cc = 0; cc < 2; cc++) {
            float v = cmin[nt][cc];
            v = fminf(v, __shfl_xor_sync(0xFFFFFFFFu, v, 4));
            v = fminf(v, __shfl_xor_sync(0xFFFFFFFFu, v, 8));
            v = fminf(v, __shfl_xor_sync(0xFFFFFFFFu, v, 16));
            cmin[nt][cc] = v;
        }

    // Cross-warp via smem (reuse staging buffer; synced above).
    float* rowbuf = sm;          // [128][4]
    float* colbuf = sm + 512;    // [128][2]
    if (tig == 0) {
        #pragma unroll
        for (int mt = 0; mt < 4; mt++)
            #pragma unroll
            for (int rr = 0; rr < 2; rr++)
                rowbuf[(wi * 64 + mt * 16 + g + rr * 8) * 4 + wj] = rmin[mt][rr];
    }
    if (g == 0) {
        #pragma unroll
        for (int nt = 0; nt < 4; nt++)
            #pragma unroll
            for (int cc = 0; cc < 2; cc++)
                colbuf[(wj * 32 + nt * 8 + 2 * tig + cc) * 2 + wi] = cmin[nt][cc];
    }
    __syncthreads();

    if (t < 128) {
        float m = fminf(fminf(rowbuf[t * 4 + 0], rowbuf[t * 4 + 1]),
                        fminf(rowbuf[t * 4 + 2], rowbuf[t * 4 + 3]));
        atomicMin((int*)&g_rowmin[(size_t)b * NN + iblk + t], __float_as_int(m));
    } else {
        int j = t - 128;
        float m = fminf(colbuf[j * 2 + 0], colbuf[j * 2 + 1]);
        atomicMin((int*)&g_colmin[(size_t)b * MM + jblk + j], __float_as_int(m));
    }
}

__global__ void reduce1_kernel() {
    __shared__ float smr[256];
    int tid = threadIdx.x;
    int i = blockIdx.x * 256 + tid;          // 128 blocks * 256 = 32768 = BB*NN
    float s = sqrtf(g_rowmin[i]) + sqrtf(g_colmin[i]);
    smr[tid] = s;
    __syncthreads();
    for (int o = 128; o > 0; o >>= 1) {
        if (tid < o) smr[tid] += smr[tid + o];
        __syncthreads();
    }
    if (tid == 0) g_partial[blockIdx.x] = smr[0];
}

__global__ void reduce2_kernel(float* __restrict__ out) {
    int tid = threadIdx.x;   // 128 threads
    float s = g_partial[tid];
    #pragma unroll
    for (int o = 16; o; o >>= 1) s += __shfl_xor_sync(0xFFFFFFFFu, s, o);
    __shared__ float w[4];
    if ((tid & 31) == 0) w[tid >> 5] = s;
    __syncthreads();
    if (tid == 0) out[0] = (w[0] + w[1] + w[2] + w[3]) / (float)(BB * NN);
}

extern "C" void kernel_launch(void* const* d_in, const int* in_sizes, int n_in,
                              void* d_out, int out_size) {
    const float* x = (const float*)d_in[0];
    const float* y = (const float*)d_in[1];
    float* out = (float*)d_out;
    (void)in_sizes; (void)n_in; (void)out_size;

    init_mins_kernel<<<(BB * NN + 255) / 256, 256>>>();

    int total_warps = 2 * BB * NN;
    norms_kernel<<<(total_warps * 32 + 255) / 256, 256>>>(x, y);

    dim3 grid(NN / TILE, MM / TILE, BB);
    chamfer_mma_kernel<<<grid, 256>>>(x, y);

    reduce1_kernel<<<128, 256>>>();
    reduce2_kernel<<<1, 128>>>(out);
}

// round 4
// speedup vs baseline: 4.7394x; 2.8185x over previous
#include <cuda_runtime.h>
#include <math.h>

#define BB 8
#define NN 4096
#define MM 4096
#define DD 128
#define KC 32          // K-chunk (floats) per pipeline stage
#define STAGE_BYTES 32768   // 2 mats * 128 rows * 128B
#define SMEM_TOTAL  65536   // 2 stages

// ---------------- scratch ----------------
__device__ float g_rowmin[BB * NN];
__device__ float g_colmin[BB * MM];
__device__ float g_x2[BB * NN];
__device__ float g_y2[BB * MM];
__device__ float g_partial[128];

__global__ void init_mins_kernel() {
    int t = blockIdx.x * blockDim.x + threadIdx.x;
    if (t < BB * NN) {
        g_rowmin[t] = __int_as_float(0x7F800000);
        g_colmin[t] = __int_as_float(0x7F800000);
    }
}

__global__ void norms_kernel(const float* __restrict__ x, const float* __restrict__ y) {
    int gw   = (blockIdx.x * blockDim.x + threadIdx.x) >> 5;
    int lane = threadIdx.x & 31;
    const float* src;
    float* dst;
    int row;
    if (gw < BB * NN) { src = x; dst = g_x2; row = gw; }
    else              { src = y; dst = g_y2; row = gw - BB * NN; }
    const float4* p = reinterpret_cast<const float4*>(src + (size_t)row * DD);
    float4 v = p[lane];
    float s = v.x * v.x + v.y * v.y + v.z * v.z + v.w * v.w;
    #pragma unroll
    for (int o = 16; o; o >>= 1) s += __shfl_xor_sync(0xFFFFFFFFu, s, o);
    if (lane == 0) dst[row] = s;
}

// ---------------- device helpers ----------------
__device__ __forceinline__ unsigned smem_u32(const void* p) {
    unsigned a;
    asm("{ .reg .u64 t; cvta.to.shared.u64 t, %1; cvt.u32.u64 %0, t; }" : "=r"(a) : "l"(p));
    return a;
}

__device__ __forceinline__ void mma_tf32(float* c, const unsigned* a, const unsigned* b) {
    asm volatile(
        "mma.sync.aligned.m16n8k8.row.col.f32.tf32.tf32.f32 "
        "{%0,%1,%2,%3}, {%4,%5,%6,%7}, {%8,%9}, {%0,%1,%2,%3};"
        : "+f"(c[0]), "+f"(c[1]), "+f"(c[2]), "+f"(c[3])
        : "r"(a[0]), "r"(a[1]), "r"(a[2]), "r"(a[3]), "r"(b[0]), "r"(b[1]));
}

__device__ __forceinline__ void ldsm4(unsigned* r, unsigned addr) {
    asm volatile("ldmatrix.sync.aligned.m8n8.x4.shared.b16 {%0,%1,%2,%3}, [%4];"
                 : "=r"(r[0]), "=r"(r[1]), "=r"(r[2]), "=r"(r[3]) : "r"(addr));
}

#define CP_ASYNC16(dst, src) \
    asm volatile("cp.async.cg.shared.global [%0], [%1], 16;" :: "r"(dst), "l"(src))
#define CP_COMMIT() asm volatile("cp.async.commit_group;" ::: "memory")
#define CP_WAIT(n)  asm volatile("cp.async.wait_group %0;" :: "n"(n) : "memory")

// ---------------- main kernel ----------------
// 128x128 tile per CTA, 256 threads, 8 warps (2x4), warp tile 64x32.
// Both x and y tiles staged row-major: 128 rows x 32 floats (128B), SW128 swizzle.
// For 128B rows the swizzle reduces to: byte_in_row ^= (row&7)<<4.
__global__ __launch_bounds__(256, 2)
void chamfer_mma_kernel(const float* __restrict__ x, const float* __restrict__ y) {
    extern __shared__ char smem[];
    const unsigned sbase = smem_u32(smem);

    const int t    = threadIdx.x;
    const int lane = t & 31;
    const int wid  = t >> 5;
    const int wi   = wid >> 2;    // 0..1 (64-row slab)
    const int wj   = wid & 3;     // 0..3 (32-col slab)
    const int g    = lane >> 2;   // 0..7
    const int tig  = lane & 3;    // 0..3

    const int b    = blockIdx.z;
    const int iblk = blockIdx.x * 128;
    const int jblk = blockIdx.y * 128;

    const float* xp = x + ((size_t)b * NN + iblk) * DD;
    const float* yp = y + ((size_t)b * MM + jblk) * DD;

    // ---- prefetch dst addresses: 16 cp.async per thread per stage (8 per mat) ----
    // idx = p*256 + t : mat = p>>2, row = (idx&1023)>>3, c4 = idx&7
    // dst byte-in-row = (c4*16) ^ ((row&7)<<4)

    // ---- ldmatrix source addressing (per thread, constant parts) ----
    const unsigned swz = (unsigned)(lane & 7) << 4;  // swizzle term, same for A and B rows
    // A: row = wi*64 + mt*16 + (lane&15), chunk-half = (lane>=16)?16:0
    const int arow_base = wi * 64 + (lane & 15);
    const unsigned ac_half = (lane & 16) ? 16u : 0u;
    // B: row = wj*32 + pr*16 + (lane&7) + ((lane&16)?8:0), chunk-half = (lane&8)?16:0
    const int brow_base = wj * 32 + (lane & 7) + ((lane & 16) ? 8 : 0);
    const unsigned bc_half = (lane & 8) ? 16u : 0u;

    float acc[4][4][4];
    #pragma unroll
    for (int mt = 0; mt < 4; mt++)
        #pragma unroll
        for (int nt = 0; nt < 4; nt++)
            #pragma unroll
            for (int r = 0; r < 4; r++) acc[mt][nt][r] = 0.0f;

    // ---- pipeline ----
    #define PREFETCH(stage, kc)                                                        \
        do {                                                                            \
            unsigned sdst = sbase + (stage) * STAGE_BYTES;                              \
            _Pragma("unroll")                                                           \
            for (int p = 0; p < 8; p++) {                                               \
                int idx = p * 256 + t;                                                  \
                int mat = p >> 2;                                                       \
                int row = (idx & 1023) >> 3;                                            \
                int c4  = idx & 7;                                                      \
                const float* gsrc = (mat ? yp : xp) + (size_t)row * DD + (kc) + c4 * 4; \
                unsigned d = sdst + mat * 16384 + row * 128 +                           \
                             (((unsigned)(c4 * 16)) ^ (((unsigned)(row & 7)) << 4));    \
                CP_ASYNC16(d, gsrc);                                                    \
            }                                                                           \
        } while (0)

    PREFETCH(0, 0);
    CP_COMMIT();

    #pragma unroll
    for (int c = 0; c < 4; c++) {
        if (c < 3) {
            PREFETCH((c + 1) & 1, (c + 1) * KC);
            CP_COMMIT();
            CP_WAIT(1);
        } else {
            CP_WAIT(0);
        }
        __syncthreads();

        const unsigned abase = sbase + (c & 1) * STAGE_BYTES;
        const unsigned bbase = abase + 16384;

        #pragma unroll
        for (int ks = 0; ks < 4; ks++) {
            const unsigned k0b = ks * 32;   // k0 * 4 bytes
            unsigned af[4][4], bq[2][4];
            #pragma unroll
            for (int mt = 0; mt < 4; mt++) {
                int row = arow_base + mt * 16;
                unsigned addr = abase + row * 128 + ((k0b + ac_half) ^ swz);
                ldsm4(af[mt], addr);
            }
            #pragma unroll
            for (int pr = 0; pr < 2; pr++) {
                int row = brow_base + pr * 16;
                unsigned addr = bbase + row * 128 + ((k0b + bc_half) ^ swz);
                ldsm4(bq[pr], addr);
            }
            #pragma unroll
            for (int mt = 0; mt < 4; mt++)
                #pragma unroll
                for (int nt = 0; nt < 4; nt++)
                    mma_tf32(acc[mt][nt], af[mt], &bq[nt >> 1][(nt & 1) * 2]);
        }
        __syncthreads();
    }

    // ---- epilogue (verified in round 2) ----
    float x2v[4][2], y2v[4][2];
    #pragma unroll
    for (int mt = 0; mt < 4; mt++) {
        x2v[mt][0] = g_x2[(size_t)b * NN + iblk + wi * 64 + mt * 16 + g];
        x2v[mt][1] = g_x2[(size_t)b * NN + iblk + wi * 64 + mt * 16 + g + 8];
    }
    #pragma unroll
    for (int nt = 0; nt < 4; nt++) {
        y2v[nt][0] = g_y2[(size_t)b * MM + jblk + wj * 32 + nt * 8 + 2 * tig];
        y2v[nt][1] = g_y2[(size_t)b * MM + jblk + wj * 32 + nt * 8 + 2 * tig + 1];
    }

    const float INF = __int_as_float(0x7F800000);
    float rmin[4][2], cmin[4][2];
    #pragma unroll
    for (int a_ = 0; a_ < 4; a_++) { rmin[a_][0] = rmin[a_][1] = INF; cmin[a_][0] = cmin[a_][1] = INF; }

    #pragma unroll
    for (int mt = 0; mt < 4; mt++)
        #pragma unroll
        for (int nt = 0; nt < 4; nt++)
            #pragma unroll
            for (int rr = 0; rr < 2; rr++)
                #pragma unroll
                for (int cc = 0; cc < 2; cc++) {
                    float d2 = fmaxf(x2v[mt][rr] + y2v[nt][cc] - 2.0f * acc[mt][nt][rr * 2 + cc], 0.0f);
                    rmin[mt][rr] = fminf(rmin[mt][rr], d2);
                    cmin[nt][cc] = fminf(cmin[nt][cc], d2);
                }

    #pragma unroll
    for (int mt = 0; mt < 4; mt++)
        #pragma unroll
        for (int rr = 0; rr < 2; rr++) {
            float v = rmin[mt][rr];
            v = fminf(v, __shfl_xor_sync(0xFFFFFFFFu, v, 1));
            v = fminf(v, __shfl_xor_sync(0xFFFFFFFFu, v, 2));
            rmin[mt][rr] = v;
        }
    #pragma unroll
    for (int nt = 0; nt < 4; nt++)
        #pragma unroll
        for (int cc = 0; cc < 2; cc++) {
            float v = cmin[nt][cc];
            v = fminf(v, __shfl_xor_sync(0xFFFFFFFFu, v, 4));
            v = fminf(v, __shfl_xor_sync(0xFFFFFFFFu, v, 8));
            v = fminf(v, __shfl_xor_sync(0xFFFFFFFFu, v, 16));
            cmin[nt][cc] = v;
        }

    float* rowbuf = reinterpret_cast<float*>(smem);          // [128][4]
    float* colbuf = reinterpret_cast<float*>(smem) + 512;    // [128][2]
    if (tig == 0) {
        #pragma unroll
        for (int mt = 0; mt < 4; mt++)
            #pragma unroll
            for (int rr = 0; rr < 2; rr++)
                rowbuf[(wi * 64 + mt * 16 + g + rr * 8) * 4 + wj] = rmin[mt][rr];
    }
    if (g == 0) {
        #pragma unroll
        for (int nt = 0; nt < 4; nt++)
            #pragma unroll
            for (int cc = 0; cc < 2; cc++)
                colbuf[(wj * 32 + nt * 8 + 2 * tig + cc) * 2 + wi] = cmin[nt][cc];
    }
    __syncthreads();

    if (t < 128) {
        float m = fminf(fminf(rowbuf[t * 4 + 0], rowbuf[t * 4 + 1]),
                        fminf(rowbuf[t * 4 + 2], rowbuf[t * 4 + 3]));
        atomicMin((int*)&g_rowmin[(size_t)b * NN + iblk + t], __float_as_int(m));
    } else if (t < 256) {
        int j = t - 128;
        float m = fminf(colbuf[j * 2 + 0], colbuf[j * 2 + 1]);
        atomicMin((int*)&g_colmin[(size_t)b * MM + jblk + j], __float_as_int(m));
    }
}

// ---------------- final reduction ----------------
__global__ void reduce1_kernel() {
    __shared__ float smr[256];
    int tid = threadIdx.x;
    int i = blockIdx.x * 256 + tid;
    float s = sqrtf(g_rowmin[i]) + sqrtf(g_colmin[i]);
    smr[tid] = s;
    __syncthreads();
    for (int o = 128; o > 0; o >>= 1) {
        if (tid < o) smr[tid] += smr[tid + o];
        __syncthreads();
    }
    if (tid == 0) g_partial[blockIdx.x] = smr[0];
}

__global__ void reduce2_kernel(float* __restrict__ out) {
    int tid = threadIdx.x;
    float s = g_partial[tid];
    #pragma unroll
    for (int o = 16; o; o >>= 1) s += __shfl_xor_sync(0xFFFFFFFFu, s, o);
    __shared__ float w[4];
    if ((tid & 31) == 0) w[tid >> 5] = s;
    __syncthreads();
    if (tid == 0) out[0] = (w[0] + w[1] + w[2] + w[3]) / (float)(BB * NN);
}

extern "C" void kernel_launch(void* const* d_in, const int* in_sizes, int n_in,
                              void* d_out, int out_size) {
    const float* x = (const float*)d_in[0];
    const float* y = (const float*)d_in[1];
    float* out = (float*)d_out;
    (void)in_sizes; (void)n_in; (void)out_size;

    cudaFuncSetAttribute(chamfer_mma_kernel, cudaFuncAttributeMaxDynamicSharedMemorySize, SMEM_TOTAL);

    init_mins_kernel<<<(BB * NN + 255) / 256, 256>>>();

    int total_warps = 2 * BB * NN;
    norms_kernel<<<(total_warps * 32 + 255) / 256, 256>>>(x, y);

    dim3 grid(NN / 128, MM / 128, BB);
    chamfer_mma_kernel<<<grid, 256, SMEM_TOTAL>>>(x, y);

    reduce1_kernel<<<128, 256>>>();
    reduce2_kernel<<<1, 128>>>(out);
}

// round 5
// speedup vs baseline: 4.9197x; 1.0380x over previous
#include <cuda_runtime.h>
#include <math.h>

#define BB 8
#define NN 4096
#define MM 4096
#define DD 128
#define KC 32                 // K-chunk (floats) per pipeline stage
#define STAGE_BYTES 32768     // 2 mats * 128 rows * 128B
#define NSTAGE 3
#define SMEM_TOTAL (NSTAGE * STAGE_BYTES)

// ---------------- scratch ----------------
__device__ float g_rowmin[BB * NN];
__device__ float g_colmin[BB * MM];
__device__ float g_x2[BB * NN];
__device__ float g_y2[BB * MM];
__device__ float g_partial[128];

// One warp per row: norms AND min-init (rowmin/x2 share indexing).
__global__ void norms_init_kernel(const float* __restrict__ x, const float* __restrict__ y) {
    int gw   = (blockIdx.x * blockDim.x + threadIdx.x) >> 5;
    int lane = threadIdx.x & 31;
    const float* src;
    float* dst;
    float* mins;
    int row;
    if (gw < BB * NN) { src = x; dst = g_x2; mins = g_rowmin; row = gw; }
    else              { src = y; dst = g_y2; mins = g_colmin; row = gw - BB * NN; }
    const float4* p = reinterpret_cast<const float4*>(src + (size_t)row * DD);
    float4 v = p[lane];
    float s = v.x * v.x + v.y * v.y + v.z * v.z + v.w * v.w;
    #pragma unroll
    for (int o = 16; o; o >>= 1) s += __shfl_xor_sync(0xFFFFFFFFu, s, o);
    if (lane == 0) {
        dst[row]  = s;
        mins[row] = __int_as_float(0x7F800000);
    }
}

// ---------------- device helpers ----------------
__device__ __forceinline__ unsigned smem_u32(const void* p) {
    unsigned a;
    asm("{ .reg .u64 t; cvta.to.shared.u64 t, %1; cvt.u32.u64 %0, t; }" : "=r"(a) : "l"(p));
    return a;
}

__device__ __forceinline__ void mma_tf32(float* c, const unsigned* a, const unsigned* b) {
    asm volatile(
        "mma.sync.aligned.m16n8k8.row.col.f32.tf32.tf32.f32 "
        "{%0,%1,%2,%3}, {%4,%5,%6,%7}, {%8,%9}, {%0,%1,%2,%3};"
        : "+f"(c[0]), "+f"(c[1]), "+f"(c[2]), "+f"(c[3])
        : "r"(a[0]), "r"(a[1]), "r"(a[2]), "r"(a[3]), "r"(b[0]), "r"(b[1]));
}

__device__ __forceinline__ void ldsm4(unsigned* r, unsigned addr) {
    asm volatile("ldmatrix.sync.aligned.m8n8.x4.shared.b16 {%0,%1,%2,%3}, [%4];"
                 : "=r"(r[0]), "=r"(r[1]), "=r"(r[2]), "=r"(r[3]) : "r"(addr));
}

#define CP_ASYNC16(dst, src) \
    asm volatile("cp.async.cg.shared.global [%0], [%1], 16;" :: "r"(dst), "l"(src))
#define CP_COMMIT() asm volatile("cp.async.commit_group;" ::: "memory")
#define CP_WAIT(n)  asm volatile("cp.async.wait_group %0;" :: "n"(n) : "memory")

// ---------------- main kernel ----------------
// 128x128 tile per CTA, 256 threads, 8 warps (2x4), warp tile 64x32.
// Tiles staged row-major 128 rows x 32 floats (128B rows), SW128 swizzle:
// byte_in_row ^= (row&7)<<4. Three pipeline stages, ONE barrier per chunk.
__global__ __launch_bounds__(256, 2)
void chamfer_mma_kernel(const float* __restrict__ x, const float* __restrict__ y) {
    extern __shared__ char smem[];
    const unsigned sbase = smem_u32(smem);

    const int t    = threadIdx.x;
    const int lane = t & 31;
    const int wid  = t >> 5;
    const int wi   = wid >> 2;    // 0..1 (64-row slab)
    const int wj   = wid & 3;     // 0..3 (32-col slab)
    const int g    = lane >> 2;   // 0..7
    const int tig  = lane & 3;    // 0..3

    const int b    = blockIdx.z;
    const int iblk = blockIdx.x * 128;
    const int jblk = blockIdx.y * 128;

    const float* xp = x + ((size_t)b * NN + iblk) * DD;
    const float* yp = y + ((size_t)b * MM + jblk) * DD;

    // ldmatrix source addressing (constant per-thread parts)
    const unsigned swz = (unsigned)(lane & 7) << 4;
    const int arow_base = wi * 64 + (lane & 15);
    const unsigned ac_half = (lane & 16) ? 16u : 0u;
    const int brow_base = wj * 32 + (lane & 7) + ((lane & 16) ? 8 : 0);
    const unsigned bc_half = (lane & 8) ? 16u : 0u;

    float acc[4][4][4];
    #pragma unroll
    for (int mt = 0; mt < 4; mt++)
        #pragma unroll
        for (int nt = 0; nt < 4; nt++)
            #pragma unroll
            for (int r = 0; r < 4; r++) acc[mt][nt][r] = 0.0f;

    #define PREFETCH(stage, kc)                                                        \
        do {                                                                            \
            unsigned sdst = sbase + (stage) * STAGE_BYTES;                              \
            _Pragma("unroll")                                                           \
            for (int p = 0; p < 8; p++) {                                               \
                int idx = p * 256 + t;                                                  \
                int mat = p >> 2;                                                       \
                int row = (idx & 1023) >> 3;                                            \
                int c4  = idx & 7;                                                      \
                const float* gsrc = (mat ? yp : xp) + (size_t)row * DD + (kc) + c4 * 4; \
                unsigned d = sdst + mat * 16384 + row * 128 +                           \
                             (((unsigned)(c4 * 16)) ^ (((unsigned)(row & 7)) << 4));    \
                CP_ASYNC16(d, gsrc);                                                    \
            }                                                                           \
        } while (0)

    PREFETCH(0, 0);
    CP_COMMIT();
    PREFETCH(1, KC);
    CP_COMMIT();

    #pragma unroll
    for (int c = 0; c < 4; c++) {
        if (c < 3) CP_WAIT(1); else CP_WAIT(0);   // stage c has landed
        __syncthreads();                          // all warps past compute(c-1); smem visible
        if (c < 2) {
            PREFETCH((c + 2) % NSTAGE, (c + 2) * KC);   // overwrites buffer read in compute(c-1)
            CP_COMMIT();
        }

        const unsigned abase = sbase + (c % NSTAGE) * STAGE_BYTES;
        const unsigned bbase = abase + 16384;

        #pragma unroll
        for (int ks = 0; ks < 4; ks++) {
            const unsigned k0b = ks * 32;
            unsigned af[4][4], bq[2][4];
            #pragma unroll
            for (int mt = 0; mt < 4; mt++) {
                int row = arow_base + mt * 16;
                ldsm4(af[mt], abase + row * 128 + ((k0b + ac_half) ^ swz));
            }
            #pragma unroll
            for (int pr = 0; pr < 2; pr++) {
                int row = brow_base + pr * 16;
                ldsm4(bq[pr], bbase + row * 128 + ((k0b + bc_half) ^ swz));
            }
            #pragma unroll
            for (int mt = 0; mt < 4; mt++)
                #pragma unroll
                for (int nt = 0; nt < 4; nt++)
                    mma_tf32(acc[mt][nt], af[mt], &bq[nt >> 1][(nt & 1) * 2]);
        }
    }

    // ---- epilogue (verified rounds 2/4) ----
    float x2v[4][2], y2v[4][2];
    #pragma unroll
    for (int mt = 0; mt < 4; mt++) {
        x2v[mt][0] = g_x2[(size_t)b * NN + iblk + wi * 64 + mt * 16 + g];
        x2v[mt][1] = g_x2[(size_t)b * NN + iblk + wi * 64 + mt * 16 + g + 8];
    }
    #pragma unroll
    for (int nt = 0; nt < 4; nt++) {
        y2v[nt][0] = g_y2[(size_t)b * MM + jblk + wj * 32 + nt * 8 + 2 * tig];
        y2v[nt][1] = g_y2[(size_t)b * MM + jblk + wj * 32 + nt * 8 + 2 * tig + 1];
    }

    const float INF = __int_as_float(0x7F800000);
    float rmin[4][2], cmin[4][2];
    #pragma unroll
    for (int a_ = 0; a_ < 4; a_++) { rmin[a_][0] = rmin[a_][1] = INF; cmin[a_][0] = cmin[a_][1] = INF; }

    #pragma unroll
    for (int mt = 0; mt < 4; mt++)
        #pragma unroll
        for (int nt = 0; nt < 4; nt++)
            #pragma unroll
            for (int rr = 0; rr < 2; rr++)
                #pragma unroll
                for (int cc = 0; cc < 2; cc++) {
                    float d2 = fmaxf(x2v[mt][rr] + y2v[nt][cc] - 2.0f * acc[mt][nt][rr * 2 + cc], 0.0f);
                    rmin[mt][rr] = fminf(rmin[mt][rr], d2);
                    cmin[nt][cc] = fminf(cmin[nt][cc], d2);
                }

    #pragma unroll
    for (int mt = 0; mt < 4; mt++)
        #pragma unroll
        for (int rr = 0; rr < 2; rr++) {
            float v = rmin[mt][rr];
            v = fminf(v, __shfl_xor_sync(0xFFFFFFFFu, v, 1));
            v = fminf(v, __shfl_xor_sync(0xFFFFFFFFu, v, 2));
            rmin[mt][rr] = v;
        }
    #pragma unroll
    for (int nt = 0; nt < 4; nt++)
        #pragma unroll
        for (int cc = 0; cc < 2; cc++) {
            float v = cmin[nt][cc];
            v = fminf(v, __shfl_xor_sync(0xFFFFFFFFu, v, 4));
            v = fminf(v, __shfl_xor_sync(0xFFFFFFFFu, v, 8));
            v = fminf(v, __shfl_xor_sync(0xFFFFFFFFu, v, 16));
            cmin[nt][cc] = v;
        }

    // Warps may still be in compute(3) reading stage buffer 0 — barrier before reuse.
    __syncthreads();
    float* rowbuf = reinterpret_cast<float*>(smem);          // [128][4]
    float* colbuf = reinterpret_cast<float*>(smem) + 512;    // [128][2]
    if (tig == 0) {
        #pragma unroll
        for (int mt = 0; mt < 4; mt++)
            #pragma unroll
            for (int rr = 0; rr < 2; rr++)
                rowbuf[(wi * 64 + mt * 16 + g + rr * 8) * 4 + wj] = rmin[mt][rr];
    }
    if (g == 0) {
        #pragma unroll
        for (int nt = 0; nt < 4; nt++)
            #pragma unroll
            for (int cc = 0; cc < 2; cc++)
                colbuf[(wj * 32 + nt * 8 + 2 * tig + cc) * 2 + wi] = cmin[nt][cc];
    }
    __syncthreads();

    if (t < 128) {
        float m = fminf(fminf(rowbuf[t * 4 + 0], rowbuf[t * 4 + 1]),
                        fminf(rowbuf[t * 4 + 2], rowbuf[t * 4 + 3]));
        atomicMin((int*)&g_rowmin[(size_t)b * NN + iblk + t], __float_as_int(m));
    } else {
        int j = t - 128;
        float m = fminf(colbuf[j * 2 + 0], colbuf[j * 2 + 1]);
        atomicMin((int*)&g_colmin[(size_t)b * MM + jblk + j], __float_as_int(m));
    }
}

// ---------------- final reduction ----------------
__global__ void reduce1_kernel() {
    __shared__ float smr[256];
    int tid = threadIdx.x;
    int i = blockIdx.x * 256 + tid;
    float s = sqrtf(g_rowmin[i]) + sqrtf(g_colmin[i]);
    smr[tid] = s;
    __syncthreads();
    for (int o = 128; o > 0; o >>= 1) {
        if (tid < o) smr[tid] += smr[tid + o];
        __syncthreads();
    }
    if (tid == 0) g_partial[blockIdx.x] = smr[0];
}

__global__ void reduce2_kernel(float* __restrict__ out) {
    int tid = threadIdx.x;
    float s = g_partial[tid];
    #pragma unroll
    for (int o = 16; o; o >>= 1) s += __shfl_xor_sync(0xFFFFFFFFu, s, o);
    __shared__ float w[4];
    if ((tid & 31) == 0) w[tid >> 5] = s;
    __syncthreads();
    if (tid == 0) out[0] = (w[0] + w[1] + w[2] + w[3]) / (float)(BB * NN);
}

extern "C" void kernel_launch(void* const* d_in, const int* in_sizes, int n_in,
                              void* d_out, int out_size) {
    const float* x = (const float*)d_in[0];
    const float* y = (const float*)d_in[1];
    float* out = (float*)d_out;
    (void)in_sizes; (void)n_in; (void)out_size;

    cudaFuncSetAttribute(chamfer_mma_kernel, cudaFuncAttributeMaxDynamicSharedMemorySize, SMEM_TOTAL);

    int total_warps = 2 * BB * NN;
    norms_init_kernel<<<(total_warps * 32 + 255) / 256, 256>>>(x, y);

    dim3 grid(NN / 128, MM / 128, BB);
    chamfer_mma_kernel<<<grid, 256, SMEM_TOTAL>>>(x, y);

    reduce1_kernel<<<128, 256>>>();
    reduce2_kernel<<<1, 128>>>(out);
}

// round 6
// speedup vs baseline: 7.1749x; 1.4584x over previous
#include <cuda_runtime.h>
#include <cuda_fp16.h>
#include <math.h>

#define BB 8
#define NN 4096
#define MM 4096
#define DD 128
#define STAGE_BYTES 32768     // 2 mats * 128 rows * 128B (64 fp16 cols)
#define NSTAGE 2
#define SMEM_TOTAL (NSTAGE * STAGE_BYTES)

// ---------------- scratch ----------------
__device__ float g_rowmin[BB * NN];
__device__ float g_colmin[BB * MM];
__device__ float g_x2[BB * NN];
__device__ float g_y2[BB * MM];
__device__ float g_partial[128];
__device__ __half g_xh[(size_t)BB * NN * DD];   // fp16 copies (8.4 MB each)
__device__ __half g_yh[(size_t)BB * MM * DD];

// One warp per row: fp32 norms (exact), min-init, and fp16 conversion.
__global__ void norms_conv_kernel(const float* __restrict__ x, const float* __restrict__ y) {
    int gw   = (blockIdx.x * blockDim.x + threadIdx.x) >> 5;
    int lane = threadIdx.x & 31;
    const float* src;
    float* dst;
    float* mins;
    __half* dsth;
    int row;
    if (gw < BB * NN) { src = x; dst = g_x2; mins = g_rowmin; dsth = g_xh; row = gw; }
    else              { src = y; dst = g_y2; mins = g_colmin; dsth = g_yh; row = gw - BB * NN; }
    const float4* p = reinterpret_cast<const float4*>(src + (size_t)row * DD);
    float4 v = p[lane];
    float s = v.x * v.x + v.y * v.y + v.z * v.z + v.w * v.w;
    #pragma unroll
    for (int o = 16; o; o >>= 1) s += __shfl_xor_sync(0xFFFFFFFFu, s, o);

    __half2 h0 = __floats2half2_rn(v.x, v.y);
    __half2 h1 = __floats2half2_rn(v.z, v.w);
    uint2 u;
    u.x = *reinterpret_cast<unsigned*>(&h0);
    u.y = *reinterpret_cast<unsigned*>(&h1);
    *reinterpret_cast<uint2*>(dsth + (size_t)row * DD + lane * 4) = u;

    if (lane == 0) {
        dst[row]  = s;
        mins[row] = __int_as_float(0x7F800000);
    }
}

// ---------------- device helpers ----------------
__device__ __forceinline__ unsigned smem_u32(const void* p) {
    unsigned a;
    asm("{ .reg .u64 t; cvta.to.shared.u64 t, %1; cvt.u32.u64 %0, t; }" : "=r"(a) : "l"(p));
    return a;
}

__device__ __forceinline__ void mma_f16(float* c, const unsigned* a, unsigned b0, unsigned b1) {
    asm volatile(
        "mma.sync.aligned.m16n8k16.row.col.f32.f16.f16.f32 "
        "{%0,%1,%2,%3}, {%4,%5,%6,%7}, {%8,%9}, {%0,%1,%2,%3};"
        : "+f"(c[0]), "+f"(c[1]), "+f"(c[2]), "+f"(c[3])
        : "r"(a[0]), "r"(a[1]), "r"(a[2]), "r"(a[3]), "r"(b0), "r"(b1));
}

__device__ __forceinline__ void ldsm4(unsigned* r, unsigned addr) {
    asm volatile("ldmatrix.sync.aligned.m8n8.x4.shared.b16 {%0,%1,%2,%3}, [%4];"
                 : "=r"(r[0]), "=r"(r[1]), "=r"(r[2]), "=r"(r[3]) : "r"(addr));
}

#define CP_ASYNC16(dst, src) \
    asm volatile("cp.async.cg.shared.global [%0], [%1], 16;" :: "r"(dst), "l"(src))
#define CP_COMMIT() asm volatile("cp.async.commit_group;" ::: "memory")
#define CP_WAIT(n)  asm volatile("cp.async.wait_group %0;" :: "n"(n) : "memory")

// ---------------- main kernel ----------------
// 128x128 tile, 256 threads (8 warps 2x4), warp tile 64x32, fp16 m16n8k16.
// K = 128 staged as 2 chunks of 64 fp16 (128B rows), SW128 swizzle:
// byte_in_row ^= (row&7)<<4.
__global__ __launch_bounds__(256, 2)
void chamfer_mma_kernel() {
    extern __shared__ char smem[];
    const unsigned sbase = smem_u32(smem);

    const int t    = threadIdx.x;
    const int lane = t & 31;
    const int wid  = t >> 5;
    const int wi   = wid >> 2;    // 0..1 (64-row slab)
    const int wj   = wid & 3;     // 0..3 (32-col slab)
    const int g    = lane >> 2;   // 0..7
    const int tig  = lane & 3;    // 0..3

    const int b    = blockIdx.z;
    const int iblk = blockIdx.x * 128;
    const int jblk = blockIdx.y * 128;

    const __half* xph = g_xh + ((size_t)b * NN + iblk) * DD;
    const __half* yph = g_yh + ((size_t)b * MM + jblk) * DD;

    // ldmatrix constant per-thread address parts
    const unsigned swz = (unsigned)(lane & 7) << 4;
    const int arow_base = wi * 64 + (lane & 15);         // A: m16 rows
    const int brow_base = wj * 32 + (lane & 7) + ((lane & 8) ? 8 : 0);  // B: n16 rows
    const unsigned khalf = (lane & 16) ? 16u : 0u;       // k8 half selector (bytes)

    float acc[4][4][4];
    #pragma unroll
    for (int mt = 0; mt < 4; mt++)
        #pragma unroll
        for (int nt = 0; nt < 4; nt++)
            #pragma unroll
            for (int r = 0; r < 4; r++) acc[mt][nt][r] = 0.0f;

    // Prefetch: per stage, 2 mats * 128 rows * 8 x 16B = 2048 chunks; 8 per thread.
    #define PREFETCH(stage, chunk)                                                     \
        do {                                                                            \
            unsigned sdst = sbase + (stage) * STAGE_BYTES;                              \
            _Pragma("unroll")                                                           \
            for (int p = 0; p < 8; p++) {                                               \
                int idx = p * 256 + t;                                                  \
                int mat = p >> 2;                                                       \
                int row = (idx & 1023) >> 3;                                            \
                int c4  = idx & 7;                                                      \
                const __half* gsrc = (mat ? yph : xph) + (size_t)row * DD + (chunk) * 64 + c4 * 8; \
                unsigned d = sdst + mat * 16384 + row * 128 +                           \
                             (((unsigned)(c4 * 16)) ^ (((unsigned)(row & 7)) << 4));    \
                CP_ASYNC16(d, gsrc);                                                    \
            }                                                                           \
        } while (0)

    PREFETCH(0, 0);
    CP_COMMIT();
    PREFETCH(1, 1);
    CP_COMMIT();

    #pragma unroll
    for (int c = 0; c < 2; c++) {
        if (c == 0) CP_WAIT(1); else CP_WAIT(0);
        __syncthreads();

        const unsigned abase = sbase + c * STAGE_BYTES;
        const unsigned bbase = abase + 16384;

        #pragma unroll
        for (int ks = 0; ks < 4; ks++) {          // k16 steps within 64-col chunk
            const unsigned k0b = ks * 32;         // k0 * 2 bytes
            unsigned af[4][4], bq[2][4];
            #pragma unroll
            for (int mt = 0; mt < 4; mt++) {
                int row = arow_base + mt * 16;
                ldsm4(af[mt], abase + row * 128 + ((k0b + khalf) ^ swz));
            }
            #pragma unroll
            for (int pr = 0; pr < 2; pr++) {      // n16 pairs covering n32
                int row = brow_base + pr * 16;
                ldsm4(bq[pr], bbase + row * 128 + ((k0b + khalf) ^ swz));
            }
            // nt even -> {r0, r2}; nt odd -> {r1, r3} of its pair
            #pragma unroll
            for (int mt = 0; mt < 4; mt++)
                #pragma unroll
                for (int nt = 0; nt < 4; nt++)
                    mma_f16(acc[mt][nt], af[mt],
                            bq[nt >> 1][nt & 1], bq[nt >> 1][(nt & 1) + 2]);
        }
    }

    // ---- epilogue (verified rounds 2/4/5; c-frag layout identical for k16) ----
    float x2v[4][2], y2v[4][2];
    #pragma unroll
    for (int mt = 0; mt < 4; mt++) {
        x2v[mt][0] = g_x2[(size_t)b * NN + iblk + wi * 64 + mt * 16 + g];
        x2v[mt][1] = g_x2[(size_t)b * NN + iblk + wi * 64 + mt * 16 + g + 8];
    }
    #pragma unroll
    for (int nt = 0; nt < 4; nt++) {
        y2v[nt][0] = g_y2[(size_t)b * MM + jblk + wj * 32 + nt * 8 + 2 * tig];
        y2v[nt][1] = g_y2[(size_t)b * MM + jblk + wj * 32 + nt * 8 + 2 * tig + 1];
    }

    const float INF = __int_as_float(0x7F800000);
    float rmin[4][2], cmin[4][2];
    #pragma unroll
    for (int a_ = 0; a_ < 4; a_++) { rmin[a_][0] = rmin[a_][1] = INF; cmin[a_][0] = cmin[a_][1] = INF; }

    #pragma unroll
    for (int mt = 0; mt < 4; mt++)
        #pragma unroll
        for (int nt = 0; nt < 4; nt++)
            #pragma unroll
            for (int rr = 0; rr < 2; rr++)
                #pragma unroll
                for (int cc = 0; cc < 2; cc++) {
                    float d2 = fmaxf(x2v[mt][rr] + y2v[nt][cc] - 2.0f * acc[mt][nt][rr * 2 + cc], 0.0f);
                    rmin[mt][rr] = fminf(rmin[mt][rr], d2);
                    cmin[nt][cc] = fminf(cmin[nt][cc], d2);
                }

    #pragma unroll
    for (int mt = 0; mt < 4; mt++)
        #pragma unroll
        for (int rr = 0; rr < 2; rr++) {
            float v = rmin[mt][rr];
            v = fminf(v, __shfl_xor_sync(0xFFFFFFFFu, v, 1));
            v = fminf(v, __shfl_xor_sync(0xFFFFFFFFu, v, 2));
            rmin[mt][rr] = v;
        }
    #pragma unroll
    for (int nt = 0; nt < 4; nt++)
        #pragma unroll
        for (int cc = 0; cc < 2; cc++) {
            float v = cmin[nt][cc];
            v = fminf(v, __shfl_xor_sync(0xFFFFFFFFu, v, 4));
            v = fminf(v, __shfl_xor_sync(0xFFFFFFFFu, v, 8));
            v = fminf(v, __shfl_xor_sync(0xFFFFFFFFu, v, 16));
            cmin[nt][cc] = v;
        }

    // Partial buffers live in stage 0; last compute read stage 1 — no hazard.
    float* rowbuf = reinterpret_cast<float*>(smem);          // [128][4]
    float* colbuf = reinterpret_cast<float*>(smem) + 512;    // [128][2]
    if (tig == 0) {
        #pragma unroll
        for (int mt = 0; mt < 4; mt++)
            #pragma unroll
            for (int rr = 0; rr < 2; rr++)
                rowbuf[(wi * 64 + mt * 16 + g + rr * 8) * 4 + wj] = rmin[mt][rr];
    }
    if (g == 0) {
        #pragma unroll
        for (int nt = 0; nt < 4; nt++)
            #pragma unroll
            for (int cc = 0; cc < 2; cc++)
                colbuf[(wj * 32 + nt * 8 + 2 * tig + cc) * 2 + wi] = cmin[nt][cc];
    }
    __syncthreads();

    if (t < 128) {
        float m = fminf(fminf(rowbuf[t * 4 + 0], rowbuf[t * 4 + 1]),
                        fminf(rowbuf[t * 4 + 2], rowbuf[t * 4 + 3]));
        atomicMin((int*)&g_rowmin[(size_t)b * NN + iblk + t], __float_as_int(m));
    } else {
        int j = t - 128;
        float m = fminf(colbuf[j * 2 + 0], colbuf[j * 2 + 1]);
        atomicMin((int*)&g_colmin[(size_t)b * MM + jblk + j], __float_as_int(m));
    }
}

// ---------------- final reduction ----------------
__global__ void reduce1_kernel() {
    __shared__ float smr[256];
    int tid = threadIdx.x;
    int i = blockIdx.x * 256 + tid;
    float s = sqrtf(g_rowmin[i]) + sqrtf(g_colmin[i]);
    smr[tid] = s;
    __syncthreads();
    for (int o = 128; o > 0; o >>= 1) {
        if (tid < o) smr[tid] += smr[tid + o];
        __syncthreads();
    }
    if (tid == 0) g_partial[blockIdx.x] = smr[0];
}

__global__ void reduce2_kernel(float* __restrict__ out) {
    int tid = threadIdx.x;
    float s = g_partial[tid];
    #pragma unroll
    for (int o = 16; o; o >>= 1) s += __shfl_xor_sync(0xFFFFFFFFu, s, o);
    __shared__ float w[4];
    if ((tid & 31) == 0) w[tid >> 5] = s;
    __syncthreads();
    if (tid == 0) out[0] = (w[0] + w[1] + w[2] + w[3]) / (float)(BB * NN);
}

extern "C" void kernel_launch(void* const* d_in, const int* in_sizes, int n_in,
                              void* d_out, int out_size) {
    const float* x = (const float*)d_in[0];
    const float* y = (const float*)d_in[1];
    float* out = (float*)d_out;
    (void)in_sizes; (void)n_in; (void)out_size;

    cudaFuncSetAttribute(chamfer_mma_kernel, cudaFuncAttributeMaxDynamicSharedMemorySize, SMEM_TOTAL);

    int total_warps = 2 * BB * NN;
    norms_conv_kernel<<<(total_warps * 32 + 255) / 256, 256>>>(x, y);

    dim3 grid(NN / 128, MM / 128, BB);
    chamfer_mma_kernel<<<grid, 256, SMEM_TOTAL>>>();

    reduce1_kernel<<<128, 256>>>();
    reduce2_kernel<<<1, 128>>>(out);
}